// round 6
// baseline (speedup 1.0000x reference)
#include <cuda_runtime.h>
#include <cuda_bf16.h>
#include <cstdint>

#define DD 64

#define MAX_E_TOTAL 2000000      // E_KG + E_UI
#define MAX_SEG     160000       // N_ENT + N_USR

// -------- device scratch (no allocations allowed) --------
static __device__ float g_score[MAX_E_TOTAL];   // holds ex = exp(score)
static __device__ float g_ssum [MAX_SEG];

__device__ __forceinline__ void red_add_f32(float* p, float v) {
    asm volatile("red.global.add.f32 [%0], %1;" :: "l"(p), "f"(v) : "memory");
}

// ---------------------------------------------------------------------------
// K0: init — zero agg outputs (float4) and segment sums
// ---------------------------------------------------------------------------
__global__ void k_init(float4* out4, int n4, int n_seg) {
    int i = blockIdx.x * blockDim.x + threadIdx.x;
    int stride = gridDim.x * blockDim.x;
    float4 z = make_float4(0.f, 0.f, 0.f, 0.f);
    for (int j = i; j < n4; j += stride) out4[j] = z;
    for (int j = i; j < n_seg; j += stride) g_ssum[j] = 0.0f;
}

// ---------------------------------------------------------------------------
// K1: FUSED heavy pass — warp-per-edge, single-line memory instructions.
//   Each warp handles 32 consecutive edges. Indices loaded coalesced once,
//   broadcast per-iteration. All row loads are 32-lane LDG.32 (exactly one
//   128B line per instruction -> no L1tex replays). Scatter is coalesced
//   scalar red.global.add.f32 (one line per instruction).
//   rel_emb / interaction_emb staged in smem (conflict-free LDS).
// ---------------------------------------------------------------------------
__global__ void __launch_bounds__(256)
k_fused(const float* __restrict__ ent,
        const float* __restrict__ usr,
        const float* __restrict__ inter,
        const float* __restrict__ rel,
        const int* __restrict__ eidx,      // [2, E_KG]
        const int* __restrict__ etype,     // [E_KG]
        const int* __restrict__ uidx,      // [E_UI]
        const int* __restrict__ iidx,      // [E_UI]
        const int* __restrict__ itype,     // [E_UI]
        float* __restrict__ out,
        int E_KG, int E_UI, int N_ENT, int N_USR,
        int N_REL, int N_ITYPE)
{
    __shared__ float s_rel[16 * DD];     // up to 16 relations
    __shared__ float s_inter[8 * DD];    // up to 8 interaction types

    for (int j = threadIdx.x; j < N_REL * DD; j += blockDim.x)
        s_rel[j] = rel[j];
    for (int j = threadIdx.x; j < N_ITYPE * DD; j += blockDim.x)
        s_inter[j] = inter[j];
    __syncthreads();

    int lane = threadIdx.x & 31;
    int warp = (blockIdx.x * blockDim.x + threadIdx.x) >> 5;
    int T = E_KG + E_UI;
    int base = warp * 32;
    if (base >= T) return;
    int n = T - base; if (n > 32) n = 32;

    // coalesced per-lane index loads for this warp's 32 edges
    int a_l = 0, b_l = 0, c_l = 0;
    int gid = base + lane;
    if (lane < n) {
        if (gid < E_KG) {
            a_l = eidx[gid];             // head
            b_l = eidx[E_KG + gid];      // tail
            c_l = etype[gid] - 1;        // relation
        } else {
            int j = gid - E_KG;
            a_l = uidx[j];               // user
            b_l = iidx[j];               // item
            c_l = itype[j];              // interaction type
        }
    }

    float* ent_agg = out;
    float* usr_agg = out + (long long)N_ENT * DD;

    #pragma unroll 4
    for (int it = 0; it < n; it++) {
        int e = base + it;
        int A = __shfl_sync(0xffffffffu, a_l, it);
        int B = __shfl_sync(0xffffffffu, b_l, it);
        int C = __shfl_sync(0xffffffffu, c_l, it);

        if (e < E_KG) {
            const float* row = ent + (long long)B * DD;
            float t0 = __ldg(row + lane);
            float t1 = __ldg(row + lane + 32);
            float r0 = s_rel[C * DD + lane];
            float r1 = s_rel[C * DD + lane + 32];
            float p = t0 * r0 + t1 * r1;
            #pragma unroll
            for (int o = 16; o > 0; o >>= 1)
                p += __shfl_xor_sync(0xffffffffu, p, o);
            float ex = __expf(p * 0.125f);
            float* dst = ent_agg + (long long)A * DD + lane;
            red_add_f32(dst,      t0 * ex);
            red_add_f32(dst + 32, t1 * ex);
            if (lane == 0) {
                g_score[e] = ex;
                atomicAdd(&g_ssum[A], ex);
            }
        } else {
            const float* irow = ent + (long long)B * DD;
            const float* urow = usr + (long long)A * DD;
            float i0 = __ldg(irow + lane);
            float i1 = __ldg(irow + lane + 32);
            float u0 = __ldg(urow + lane);
            float u1 = __ldg(urow + lane + 32);
            float v0 = s_inter[C * DD + lane];
            float v1 = s_inter[C * DD + lane + 32];
            float p = i0 * u0 * v0 + i1 * u1 * v1;
            #pragma unroll
            for (int o = 16; o > 0; o >>= 1)
                p += __shfl_xor_sync(0xffffffffu, p, o);
            float ex = __expf(p);
            float* dst = usr_agg + (long long)A * DD + lane;
            red_add_f32(dst,      i0 * ex);
            red_add_f32(dst + 32, i1 * ex);
            if (lane == 0) {
                g_score[e] = ex;
                atomicAdd(&g_ssum[N_ENT + A], ex);
            }
        }
    }
}

// ---------------------------------------------------------------------------
// K2: merged tail. [0, n4): normalize agg rows; [n4, n4+T): edge weights.
// ---------------------------------------------------------------------------
__global__ void k_tail(float4* __restrict__ out4, int n4,
                       const int* __restrict__ eidx,
                       const int* __restrict__ uidx,
                       float* __restrict__ out,
                       int E_KG, int E_UI, int N_ENT, int N_USR)
{
    int i = blockIdx.x * blockDim.x + threadIdx.x;
    if (i < n4) {
        int seg = i >> 4;
        float s = g_ssum[seg];
        float inv = (s > 0.0f) ? __frcp_rn(s) : 0.0f;
        float4 v = out4[i];
        v.x *= inv; v.y *= inv; v.z *= inv; v.w *= inv;
        out4[i] = v;
    } else {
        int e = i - n4;
        int T = E_KG + E_UI;
        if (e >= T) return;
        float* att_out = out + (long long)(N_ENT + N_USR) * DD;
        float* w1_out  = att_out + E_UI;
        if (e < E_KG) {
            int head = eidx[e];
            w1_out[e] = g_score[e] * __frcp_rn(g_ssum[head]);
        } else {
            int j = e - E_KG;
            int u = uidx[j];
            att_out[j] = g_score[e] * __frcp_rn(g_ssum[N_ENT + u]);
        }
    }
}

// ---------------------------------------------------------------------------
extern "C" void kernel_launch(void* const* d_in, const int* in_sizes, int n_in,
                              void* d_out, int out_size)
{
    const float* ent   = (const float*)d_in[0];
    const float* usr   = (const float*)d_in[1];
    const float* inter = (const float*)d_in[2];
    const float* rel   = (const float*)d_in[3];
    const int* eidx  = (const int*)d_in[4];
    const int* etype = (const int*)d_in[5];
    const int* uidx  = (const int*)d_in[6];
    const int* iidx  = (const int*)d_in[7];
    const int* itype = (const int*)d_in[8];
    float* out = (float*)d_out;

    int N_ENT   = in_sizes[0] / DD;
    int N_USR   = in_sizes[1] / DD;
    int N_ITYPE = in_sizes[2] / DD;
    int N_REL   = in_sizes[3] / DD;
    int E_KG    = in_sizes[5];
    int E_UI    = in_sizes[6];
    int T = E_KG + E_UI;
    int n_agg = (N_ENT + N_USR) * DD;
    int n_seg = N_ENT + N_USR;
    int n4 = n_agg / 4;

    const int B = 256;

    k_init<<<2048, B>>>((float4*)out, n4, n_seg);

    // one warp per 32 edges
    int warps = (T + 31) / 32;
    int g = (warps * 32 + B - 1) / B;
    k_fused<<<g, B>>>(ent, usr, inter, rel,
                      eidx, etype, uidx, iidx, itype,
                      out, E_KG, E_UI, N_ENT, N_USR, N_REL, N_ITYPE);

    int tail_work = n4 + T;
    k_tail<<<(tail_work + B - 1) / B, B>>>((float4*)out, n4, eidx, uidx, out,
                                           E_KG, E_UI, N_ENT, N_USR);
}

// round 8
// speedup vs baseline: 1.0805x; 1.0805x over previous
#include <cuda_runtime.h>
#include <cuda_bf16.h>
#include <cstdint>

#define DD 64

#define MAX_E_TOTAL 2000000      // E_KG + E_UI
#define MAX_SEG     160000       // N_ENT + N_USR

// -------- device scratch (no allocations allowed) --------
static __device__ float g_score[MAX_E_TOTAL];   // holds ex = exp(score)
static __device__ float g_ssum [MAX_SEG];

__device__ __forceinline__ void red_add_v4(float* p, float4 v) {
    asm volatile("red.global.add.v4.f32 [%0], {%1,%2,%3,%4};"
                 :: "l"(p), "f"(v.x), "f"(v.y), "f"(v.z), "f"(v.w) : "memory");
}
__device__ __forceinline__ float dot4(float4 a, float4 b) {
    return a.x * b.x + a.y * b.y + a.z * b.z + a.w * b.w;
}
__device__ __forceinline__ float dot4x3(float4 a, float4 b, float4 c) {
    return a.x * b.x * c.x + a.y * b.y * c.y + a.z * b.z * c.z + a.w * b.w * c.w;
}

// ---------------------------------------------------------------------------
// K0: init — zero agg outputs (float4) and segment sums
// ---------------------------------------------------------------------------
__global__ void k_init(float4* out4, int n4, int n_seg) {
    int i = blockIdx.x * blockDim.x + threadIdx.x;
    int stride = gridDim.x * blockDim.x;
    float4 z = make_float4(0.f, 0.f, 0.f, 0.f);
    for (int j = i; j < n4; j += stride) out4[j] = z;
    for (int j = i; j < n_seg; j += stride) g_ssum[j] = 0.0f;
}

// ---------------------------------------------------------------------------
// K1: FUSED heavy pass. 8 threads per edge, 2x float4 per thread (R3 layout).
//   rel/inter rows staged in smem (removes 2 scattered LDG.128 per edge).
//   Dot reduced with 3-step shfl butterfly.
// ---------------------------------------------------------------------------
__global__ void __launch_bounds__(256)
k_fused(const float4* __restrict__ ent4,
        const float4* __restrict__ usr4,
        const float4* __restrict__ inter4,
        const float4* __restrict__ rel4,
        const int* __restrict__ eidx,      // [2, E_KG]
        const int* __restrict__ etype,     // [E_KG]
        const int* __restrict__ uidx,      // [E_UI]
        const int* __restrict__ iidx,      // [E_UI]
        const int* __restrict__ itype,     // [E_UI]
        float* __restrict__ out,
        int E_KG, int E_UI, int N_ENT, int N_USR,
        int N_REL, int N_ITYPE)
{
    __shared__ float4 s_rel[16 * 16];    // up to 16 relations x 16 float4
    __shared__ float4 s_inter[8 * 16];   // up to 8 itypes x 16 float4

    for (int j = threadIdx.x; j < N_REL * 16; j += blockDim.x)
        s_rel[j] = rel4[j];
    for (int j = threadIdx.x; j < N_ITYPE * 16; j += blockDim.x)
        s_inter[j] = inter4[j];
    __syncthreads();

    long long tid = (long long)blockIdx.x * blockDim.x + threadIdx.x;
    int e = (int)(tid >> 3);
    int c = (int)(tid & 7);
    int T = E_KG + E_UI;
    if (e >= T) return;

    float* ent_agg = out;
    float* usr_agg = out + (long long)N_ENT * DD;

    if (e < E_KG) {
        int head = eidx[e];
        int tail = eidx[E_KG + e];
        int rt   = etype[e] - 1;
        const float4* nrow = ent4 + (long long)tail * 16;
        float4 nv0 = nrow[c];
        float4 nv1 = nrow[c + 8];
        float4 rv0 = s_rel[rt * 16 + c];
        float4 rv1 = s_rel[rt * 16 + c + 8];
        float p = dot4(nv0, rv0) + dot4(nv1, rv1);
        #pragma unroll
        for (int o = 4; o > 0; o >>= 1)
            p += __shfl_xor_sync(0xffffffffu, p, o);
        float ex = __expf(p * 0.125f);
        float* dst = ent_agg + (long long)head * DD;
        red_add_v4(dst + c * 4,
                   make_float4(nv0.x * ex, nv0.y * ex, nv0.z * ex, nv0.w * ex));
        red_add_v4(dst + (c + 8) * 4,
                   make_float4(nv1.x * ex, nv1.y * ex, nv1.z * ex, nv1.w * ex));
        if (c == 0) {
            g_score[e] = ex;
            atomicAdd(&g_ssum[head], ex);
        }
    } else {
        int i  = e - E_KG;
        int u  = uidx[i];
        int it = iidx[i];
        int ty = itype[i];
        const float4* irow = ent4 + (long long)it * 16;
        const float4* urow = usr4 + (long long)u * 16;
        float4 iv0 = irow[c];
        float4 iv1 = irow[c + 8];
        float4 uv0 = urow[c];
        float4 uv1 = urow[c + 8];
        float4 tv0 = s_inter[ty * 16 + c];
        float4 tv1 = s_inter[ty * 16 + c + 8];
        float p = dot4x3(iv0, uv0, tv0) + dot4x3(iv1, uv1, tv1);
        #pragma unroll
        for (int o = 4; o > 0; o >>= 1)
            p += __shfl_xor_sync(0xffffffffu, p, o);
        float ex = __expf(p);
        float* dst = usr_agg + (long long)u * DD;
        red_add_v4(dst + c * 4,
                   make_float4(iv0.x * ex, iv0.y * ex, iv0.z * ex, iv0.w * ex));
        red_add_v4(dst + (c + 8) * 4,
                   make_float4(iv1.x * ex, iv1.y * ex, iv1.z * ex, iv1.w * ex));
        if (c == 0) {
            g_score[e] = ex;
            atomicAdd(&g_ssum[N_ENT + u], ex);
        }
    }
}

// ---------------------------------------------------------------------------
// K2: merged tail. [0, n4): normalize agg rows; [n4, n4+T): edge weights.
// ---------------------------------------------------------------------------
__global__ void k_tail(float4* __restrict__ out4, int n4,
                       const int* __restrict__ eidx,
                       const int* __restrict__ uidx,
                       float* __restrict__ out,
                       int E_KG, int E_UI, int N_ENT, int N_USR)
{
    int i = blockIdx.x * blockDim.x + threadIdx.x;
    if (i < n4) {
        int seg = i >> 4;
        float s = g_ssum[seg];
        float inv = (s > 0.0f) ? __frcp_rn(s) : 0.0f;
        float4 v = out4[i];
        v.x *= inv; v.y *= inv; v.z *= inv; v.w *= inv;
        out4[i] = v;
    } else {
        int e = i - n4;
        int T = E_KG + E_UI;
        if (e >= T) return;
        float* att_out = out + (long long)(N_ENT + N_USR) * DD;
        float* w1_out  = att_out + E_UI;
        if (e < E_KG) {
            int head = eidx[e];
            w1_out[e] = g_score[e] * __frcp_rn(g_ssum[head]);
        } else {
            int j = e - E_KG;
            int u = uidx[j];
            att_out[j] = g_score[e] * __frcp_rn(g_ssum[N_ENT + u]);
        }
    }
}

// ---------------------------------------------------------------------------
extern "C" void kernel_launch(void* const* d_in, const int* in_sizes, int n_in,
                              void* d_out, int out_size)
{
    const float4* ent4   = (const float4*)d_in[0];
    const float4* usr4   = (const float4*)d_in[1];
    const float4* inter4 = (const float4*)d_in[2];
    const float4* rel4   = (const float4*)d_in[3];
    const int* eidx  = (const int*)d_in[4];
    const int* etype = (const int*)d_in[5];
    const int* uidx  = (const int*)d_in[6];
    const int* iidx  = (const int*)d_in[7];
    const int* itype = (const int*)d_in[8];
    float* out = (float*)d_out;

    int N_ENT   = in_sizes[0] / DD;
    int N_USR   = in_sizes[1] / DD;
    int N_ITYPE = in_sizes[2] / DD;
    int N_REL   = in_sizes[3] / DD;
    int E_KG    = in_sizes[5];
    int E_UI    = in_sizes[6];
    int T = E_KG + E_UI;
    int n_agg = (N_ENT + N_USR) * DD;
    int n_seg = N_ENT + N_USR;
    int n4 = n_agg / 4;

    const int B = 256;

    k_init<<<2048, B>>>((float4*)out, n4, n_seg);

    long long wide = (long long)T * 8;
    int g_wide = (int)((wide + B - 1) / B);
    k_fused<<<g_wide, B>>>(ent4, usr4, inter4, rel4,
                           eidx, etype, uidx, iidx, itype,
                           out, E_KG, E_UI, N_ENT, N_USR, N_REL, N_ITYPE);

    int tail_work = n4 + T;
    k_tail<<<(tail_work + B - 1) / B, B>>>((float4*)out, n4, eidx, uidx, out,
                                           E_KG, E_UI, N_ENT, N_USR);
}

// round 9
// speedup vs baseline: 1.3266x; 1.2278x over previous
#include <cuda_runtime.h>
#include <cuda_bf16.h>
#include <cstdint>

#define DD 64

#define MAX_E_TOTAL 2000000      // E_KG + E_UI
#define MAX_SEG     160000       // N_ENT + N_USR

// -------- device scratch (no allocations allowed) --------
static __device__ float g_score[MAX_E_TOTAL];   // holds ex = exp(score)
static __device__ float g_ssum [MAX_SEG];

__device__ __forceinline__ void red_add_v4(float* p, float4 v) {
    asm volatile("red.global.add.v4.f32 [%0], {%1,%2,%3,%4};"
                 :: "l"(p), "f"(v.x), "f"(v.y), "f"(v.z), "f"(v.w) : "memory");
}
__device__ __forceinline__ float dot4(float4 a, float4 b) {
    return a.x * b.x + a.y * b.y + a.z * b.z + a.w * b.w;
}
__device__ __forceinline__ float dot4x3(float4 a, float4 b, float4 c) {
    return a.x * b.x * c.x + a.y * b.y * c.y + a.z * b.z * c.z + a.w * b.w * c.w;
}

// ---------------------------------------------------------------------------
// K0: init — zero agg outputs (float4) and segment sums
// ---------------------------------------------------------------------------
__global__ void k_init(float4* out4, int n4, int n_seg) {
    int i = blockIdx.x * blockDim.x + threadIdx.x;
    int stride = gridDim.x * blockDim.x;
    float4 z = make_float4(0.f, 0.f, 0.f, 0.f);
    for (int j = i; j < n4; j += stride) out4[j] = z;
    for (int j = i; j < n_seg; j += stride) g_ssum[j] = 0.0f;
}

// ---------------------------------------------------------------------------
// K1: FUSED heavy pass. 8 threads per edge, 2x float4 per thread (R3 layout),
//   PERSISTENT blocks with grid-stride over edges so the smem staging of
//   rel/inter tables (6KB) is amortized over ~1000 edges per block instead
//   of being refilled by 62.5k blocks (R8's 375MB mistake).
// ---------------------------------------------------------------------------
__global__ void __launch_bounds__(256)
k_fused(const float4* __restrict__ ent4,
        const float4* __restrict__ usr4,
        const float4* __restrict__ inter4,
        const float4* __restrict__ rel4,
        const int* __restrict__ eidx,      // [2, E_KG]
        const int* __restrict__ etype,     // [E_KG]
        const int* __restrict__ uidx,      // [E_UI]
        const int* __restrict__ iidx,      // [E_UI]
        const int* __restrict__ itype,     // [E_UI]
        float* __restrict__ out,
        int E_KG, int E_UI, int N_ENT, int N_USR,
        int N_REL, int N_ITYPE)
{
    __shared__ float4 s_rel[16 * 16];    // up to 16 relations x 16 float4
    __shared__ float4 s_inter[8 * 16];   // up to 8 itypes x 16 float4

    for (int j = threadIdx.x; j < N_REL * 16; j += blockDim.x)
        s_rel[j] = rel4[j];
    for (int j = threadIdx.x; j < N_ITYPE * 16; j += blockDim.x)
        s_inter[j] = inter4[j];
    __syncthreads();

    int T = E_KG + E_UI;
    int c = threadIdx.x & 7;
    int e0     = (int)(((long long)blockIdx.x * blockDim.x + threadIdx.x) >> 3);
    int estep  = (int)(((long long)gridDim.x * blockDim.x) >> 3);

    float* ent_agg = out;
    float* usr_agg = out + (long long)N_ENT * DD;

    for (int e = e0; e < T; e += estep) {
        if (e < E_KG) {
            int head = eidx[e];
            int tail = eidx[E_KG + e];
            int rt   = etype[e] - 1;
            const float4* nrow = ent4 + (long long)tail * 16;
            float4 nv0 = nrow[c];
            float4 nv1 = nrow[c + 8];
            float4 rv0 = s_rel[rt * 16 + c];
            float4 rv1 = s_rel[rt * 16 + c + 8];
            float p = dot4(nv0, rv0) + dot4(nv1, rv1);
            #pragma unroll
            for (int o = 4; o > 0; o >>= 1)
                p += __shfl_xor_sync(0xffffffffu, p, o);
            float ex = __expf(p * 0.125f);
            float* dst = ent_agg + (long long)head * DD;
            red_add_v4(dst + c * 4,
                       make_float4(nv0.x * ex, nv0.y * ex, nv0.z * ex, nv0.w * ex));
            red_add_v4(dst + (c + 8) * 4,
                       make_float4(nv1.x * ex, nv1.y * ex, nv1.z * ex, nv1.w * ex));
            if (c == 0) {
                g_score[e] = ex;
                atomicAdd(&g_ssum[head], ex);
            }
        } else {
            int i  = e - E_KG;
            int u  = uidx[i];
            int it = iidx[i];
            int ty = itype[i];
            const float4* irow = ent4 + (long long)it * 16;
            const float4* urow = usr4 + (long long)u * 16;
            float4 iv0 = irow[c];
            float4 iv1 = irow[c + 8];
            float4 uv0 = urow[c];
            float4 uv1 = urow[c + 8];
            float4 tv0 = s_inter[ty * 16 + c];
            float4 tv1 = s_inter[ty * 16 + c + 8];
            float p = dot4x3(iv0, uv0, tv0) + dot4x3(iv1, uv1, tv1);
            #pragma unroll
            for (int o = 4; o > 0; o >>= 1)
                p += __shfl_xor_sync(0xffffffffu, p, o);
            float ex = __expf(p);
            float* dst = usr_agg + (long long)u * DD;
            red_add_v4(dst + c * 4,
                       make_float4(iv0.x * ex, iv0.y * ex, iv0.z * ex, iv0.w * ex));
            red_add_v4(dst + (c + 8) * 4,
                       make_float4(iv1.x * ex, iv1.y * ex, iv1.z * ex, iv1.w * ex));
            if (c == 0) {
                g_score[e] = ex;
                atomicAdd(&g_ssum[N_ENT + u], ex);
            }
        }
    }
}

// ---------------------------------------------------------------------------
// K2: merged tail. [0, n4): normalize agg rows; [n4, n4+T): edge weights.
// ---------------------------------------------------------------------------
__global__ void k_tail(float4* __restrict__ out4, int n4,
                       const int* __restrict__ eidx,
                       const int* __restrict__ uidx,
                       float* __restrict__ out,
                       int E_KG, int E_UI, int N_ENT, int N_USR)
{
    int i = blockIdx.x * blockDim.x + threadIdx.x;
    if (i < n4) {
        int seg = i >> 4;
        float s = g_ssum[seg];
        float inv = (s > 0.0f) ? __frcp_rn(s) : 0.0f;
        float4 v = out4[i];
        v.x *= inv; v.y *= inv; v.z *= inv; v.w *= inv;
        out4[i] = v;
    } else {
        int e = i - n4;
        int T = E_KG + E_UI;
        if (e >= T) return;
        float* att_out = out + (long long)(N_ENT + N_USR) * DD;
        float* w1_out  = att_out + E_UI;
        if (e < E_KG) {
            int head = eidx[e];
            w1_out[e] = g_score[e] * __frcp_rn(g_ssum[head]);
        } else {
            int j = e - E_KG;
            int u = uidx[j];
            att_out[j] = g_score[e] * __frcp_rn(g_ssum[N_ENT + u]);
        }
    }
}

// ---------------------------------------------------------------------------
extern "C" void kernel_launch(void* const* d_in, const int* in_sizes, int n_in,
                              void* d_out, int out_size)
{
    const float4* ent4   = (const float4*)d_in[0];
    const float4* usr4   = (const float4*)d_in[1];
    const float4* inter4 = (const float4*)d_in[2];
    const float4* rel4   = (const float4*)d_in[3];
    const int* eidx  = (const int*)d_in[4];
    const int* etype = (const int*)d_in[5];
    const int* uidx  = (const int*)d_in[6];
    const int* iidx  = (const int*)d_in[7];
    const int* itype = (const int*)d_in[8];
    float* out = (float*)d_out;

    int N_ENT   = in_sizes[0] / DD;
    int N_USR   = in_sizes[1] / DD;
    int N_ITYPE = in_sizes[2] / DD;
    int N_REL   = in_sizes[3] / DD;
    int E_KG    = in_sizes[5];
    int E_UI    = in_sizes[6];
    int T = E_KG + E_UI;
    int n_agg = (N_ENT + N_USR) * DD;
    int n_seg = N_ENT + N_USR;
    int n4 = n_agg / 4;

    const int B = 256;

    k_init<<<2048, B>>>((float4*)out, n4, n_seg);

    // persistent grid: 2048 blocks, each warp grid-strides over edge-groups
    k_fused<<<2048, B>>>(ent4, usr4, inter4, rel4,
                         eidx, etype, uidx, iidx, itype,
                         out, E_KG, E_UI, N_ENT, N_USR, N_REL, N_ITYPE);

    int tail_work = n4 + T;
    k_tail<<<(tail_work + B - 1) / B, B>>>((float4*)out, n4, eidx, uidx, out,
                                           E_KG, E_UI, N_ENT, N_USR);
}